// round 1
// baseline (speedup 1.0000x reference)
#include <cuda_runtime.h>

// CTC forward loss, T=512, N=32, C=8000, S=40 (Se = 2S+1 = 81).
// One block per batch element, one thread per CTC state.
// Alpha recurrence in log2 domain (exact: LOG_TINY = ln(2^-126) -> -126.0 in log2).
// Global gathers hidden by a depth-8 register prefetch ring.

#define TT 512
#define NB 32
#define CC 8000
#define SS 40
#define SE 81        // 2*SS + 1
#define PF 8         // prefetch depth

#define NEGF     (-1.0e30f)
#define INV_LN2  1.44269504088896341f
#define LN2      0.69314718055994531f

__device__ __forceinline__ float ex2f_(float x) {
    float y; asm("ex2.approx.ftz.f32 %0, %1;" : "=f"(y) : "f"(x)); return y;
}
__device__ __forceinline__ float lg2f_(float x) {
    float y; asm("lg2.approx.ftz.f32 %0, %1;" : "=f"(y) : "f"(x)); return y;
}

__global__ __launch_bounds__(96, 1)
void ctc_fwd_kernel(const float* __restrict__ lp,      // (T, N, C)
                    const int*   __restrict__ targets, // (N, S)
                    const int*   __restrict__ tgt_len, // (N,)
                    float*       __restrict__ out)     // (N,)
{
    const int n   = blockIdx.x;
    const int tid = threadIdx.x;
    const int s   = (tid < SE) ? tid : (SE - 1);   // clamp extras to state 80 (benign dup work)

    __shared__ float abuf[2][SE + 2];   // [0],[1] are -inf pads; state s lives at s+2

    if (tid < 2) { abuf[0][tid] = NEGF; abuf[1][tid] = NEGF; }

    // Expanded label for this state: even -> blank(0), odd -> targets[(s-1)/2].
    int  cls  = 0;
    bool skip = false;
    if (s & 1) {
        cls = targets[n * SS + (s >> 1)];
        if (s >= 3) skip = (cls != targets[n * SS + ((s - 3) >> 1)]);
    }

    const unsigned base   = (unsigned)n * CC + (unsigned)cls;
    const unsigned stride = (unsigned)NB * CC;     // 256000 floats per timestep

    // t = 0 init (log2 domain). log2(float32 tiny) == -126 exactly.
    {
        float l0 = __ldg(lp + base) * INV_LN2;
        float a0 = (s <= 1) ? l0 : -126.0f;
        abuf[0][s + 2] = a0;
    }

    // Preload lp for t = 1..PF into the ring.
    float ring[PF];
#pragma unroll
    for (int j = 0; j < PF; ++j)
        ring[j] = __ldg(lp + base + (unsigned)(j + 1) * stride);

    __syncthreads();

    int p = 0;
#pragma unroll 8
    for (int t = 1; t < TT; ++t) {
        const int j = (t - 1) & (PF - 1);
        const float l = ring[j] * INV_LN2;
        if (t + PF < TT)
            ring[j] = __ldg(lp + base + (unsigned)(t + PF) * stride);

        const float a  = abuf[p][s + 2];
        const float a1 = abuf[p][s + 1];                  // pad handles s==0
        const float a2 = skip ? abuf[p][s] : NEGF;        // disabled -> exp2 -> 0 exactly

        const float m    = fmaxf(fmaxf(a, a1), a2);
        const float sum  = ex2f_(a - m) + ex2f_(a1 - m) + ex2f_(a2 - m);
        const float anew = m + lg2f_(sum) + l;

        abuf[p ^ 1][s + 2] = anew;
        __syncthreads();
        p ^= 1;
    }

    if (tid == 0) {
        const int   L    = tgt_len[n];
        const int   len  = 2 * L + 1;
        const float al   = abuf[p][len - 1 + 2];
        const float ap   = abuf[p][len - 2 + 2];
        const float x    = fmaxf(al, ap);
        const float y    = fminf(al, ap);
        const float loss = (x + lg2f_(1.0f + ex2f_(y - x))) * LN2;  // back to ln domain
        out[n] = -loss / (float)L;
    }
}

extern "C" void kernel_launch(void* const* d_in, const int* in_sizes, int n_in,
                              void* d_out, int out_size) {
    const float* lp      = (const float*)d_in[0];  // log_probs (T, N, C)
    const int*   targets = (const int*)  d_in[1];  // (N, S)
    // d_in[2] = input_lengths — reference ignores them (always full T)
    const int*   tlen    = (const int*)  d_in[3];  // (N,)
    ctc_fwd_kernel<<<NB, 96>>>(lp, targets, tlen, (float*)d_out);
}